// round 5
// baseline (speedup 1.0000x reference)
#include <cuda_runtime.h>

#define BATCH 256

// ---------------- intermediate scratch (device globals; no allocs) ----------
__device__ float g_h1[BATCH*3*15*15*15*15];   // 155.5 MB
__device__ float g_h2[BATCH*3*12*12*12*12];   //  63.7 MB
__device__ float g_h3[BATCH*4*9*9*9*9];       //  26.9 MB
__device__ float g_h4[BATCH*5*6*6*6*6];       //   6.6 MB
__device__ float g_h5[BATCH*5*4*4*4*4];       //   1.3 MB

typedef unsigned long long u64;

__device__ __forceinline__ u64 pk2(float lo, float hi) {
    u64 d; asm("mov.b64 %0, {%1, %2};" : "=l"(d) : "f"(lo), "f"(hi)); return d;
}
__device__ __forceinline__ void unpk2(u64 v, float& lo, float& hi) {
    asm("mov.b64 {%0, %1}, %2;" : "=f"(lo), "=f"(hi) : "l"(v));
}
__device__ __forceinline__ u64 fma2(u64 a, u64 b, u64 c) {
    u64 d; asm("fma.rn.f32x2 %0, %1, %2, %3;" : "=l"(d) : "l"(a), "l"(b), "l"(c));
    return d;
}

// ---------------------------------------------------------------------------
// Batch-paired 4D conv, TY=1 exact tiling, LDS.128 everywhere.
// Block = (batch-pair, oy, z-tile). Tile = full (W,X), one y-window (K rows),
// TZIP-padded z-window; all u64 (b0,b1) interleaved pairs. Weights staged
// per-cin-chunk as duplicated u64 pairs. Inner loop: LDS.128 + fma.rn.f32x2.
// ---------------------------------------------------------------------------
template<int CIN,int COUT,int S,int K,int TZ,int TZIP,int BDIM,int MINB>
__global__ __launch_bounds__(BDIM, MINB)
void conv4d_t1_bp(const float* __restrict__ in, const float* __restrict__ wt,
                  const float* __restrict__ bias, float* __restrict__ out)
{
    constexpr int O   = S - K + 1;
    constexpr int NTZ = O / TZ;
    static_assert(O % TZ == 0, "exact z tiling");
    constexpr int TZI = TZ + K - 1;
    static_assert(TZIP >= TZI && TZIP % 2 == 0, "padded even z window");
    static_assert(BDIM >= O * O, "one pos per thread");
    constexpr int K4  = K * K * K * K;
    constexpr int ISZ = S * S * K * TZIP;   // u64 entries per cin chunk
    constexpr int WCH = COUT * K4;          // u64 entries per cin chunk (even)
    static_assert(WCH % 2 == 0 && (K * COUT) % 2 == 0, "aligned weight rows");

    extern __shared__ u64 smu[];
    u64* sw2 = smu;            // weight pairs for current cin
    u64* siu = smu + WCH;      // batch-interleaved input window

    const int tid = threadIdx.x;
    int bid = blockIdx.x;
    const int tzb = bid % NTZ; bid /= NTZ;
    const int oy  = bid % O;
    const int bp  = bid / O;
    const int z0 = tzb * TZ;

    const int pos = tid;
    const int ow  = pos / O, ox = pos - ow * O;
    const bool active = (pos < O * O);

    u64 acc[COUT][TZ];
    #pragma unroll
    for (int c = 0; c < COUT; c++) {
        float bv = bias[c];
        u64 bpk = pk2(bv, bv);
        #pragma unroll
        for (int tz = 0; tz < TZ; tz++) acc[c][tz] = bpk;
    }

    const float* inb0 = in + (size_t)(2*bp)     * CIN * S * S * S * S;
    const float* inb1 = in + (size_t)(2*bp + 1) * CIN * S * S * S * S;

    for (int cin = 0; cin < CIN; cin++) {
        __syncthreads();
        // stage weights: gmem [c][cin][k4] -> smem [k4][c] dup pairs
        for (int i = tid; i < WCH; i += BDIM) {
            int c = i / K4;
            int r = i - c * K4;
            float w = wt[(c * CIN + cin) * K4 + r];
            sw2[r * COUT + c] = pk2(w, w);
        }
        // stage input window [ww][xx][iy<K][zz<TZIP]
        #pragma unroll 2
        for (int i = tid; i < ISZ; i += BDIM) {
            int zz = i % TZIP; int t = i / TZIP;
            int iy = t % K;    t /= K;
            int xx = t % S;    int ww = t / S;
            int gy = oy + iy, gz = z0 + zz;       // gy always < S (exact tiling)
            float v0 = 0.f, v1 = 0.f;
            if (gz < S) {
                size_t gidx = ((((size_t)cin * S + ww) * S + xx) * S + gy) * S + gz;
                v0 = inb0[gidx];
                v1 = inb1[gidx];
            }
            siu[i] = pk2(v0, v1);
        }
        __syncthreads();

        if (active) {
            #pragma unroll 1
            for (int kw = 0; kw < K; kw++)
            #pragma unroll 1
            for (int kx = 0; kx < K; kx++) {
                const u64* ip = siu + ((ow + kw) * S + ox + kx) * K * TZIP;
                const u64* wb = sw2 + ((kw * K + kx) * K * K) * COUT;
                #pragma unroll
                for (int ky = 0; ky < K; ky++) {
                    u64 wr[K * COUT];
                    const ulonglong2* w2p =
                        reinterpret_cast<const ulonglong2*>(wb + ky * K * COUT);
                    #pragma unroll
                    for (int i = 0; i < K * COUT / 2; i++) {
                        ulonglong2 v = w2p[i];
                        wr[2*i] = v.x; wr[2*i+1] = v.y;
                    }
                    u64 row[TZIP];
                    const ulonglong2* r2p =
                        reinterpret_cast<const ulonglong2*>(ip + ky * TZIP);
                    #pragma unroll
                    for (int i = 0; i < TZIP / 2; i++) {
                        ulonglong2 v = r2p[i];
                        row[2*i] = v.x; row[2*i+1] = v.y;
                    }
                    #pragma unroll
                    for (int kz = 0; kz < K; kz++)
                    #pragma unroll
                    for (int tz = 0; tz < TZ; tz++)
                    #pragma unroll
                    for (int c = 0; c < COUT; c++)
                        acc[c][tz] = fma2(row[tz + kz], wr[kz*COUT + c],
                                          acc[c][tz]);
                }
            }
        }
    }

    if (active) {
        float* outb0 = out + (size_t)(2*bp)     * COUT * O * O * O * O;
        float* outb1 = out + (size_t)(2*bp + 1) * COUT * O * O * O * O;
        #pragma unroll
        for (int c = 0; c < COUT; c++)
        #pragma unroll
        for (int tz = 0; tz < TZ; tz++) {
            float lo, hi; unpk2(acc[c][tz], lo, hi);
            size_t idx = (((size_t)(c * O + ow) * O + ox) * O + oy) * O + z0 + tz;
            outb0[idx] = fmaxf(lo, 0.f);
            outb1[idx] = fmaxf(hi, 0.f);
        }
    }
}

// ---------------------------------------------------------------------------
// Batch-paired whole-spatial conv (L4), W-split, z padded for LDS.128.
// Thread = (owl,ox,oy); full Z accumulators.
// ---------------------------------------------------------------------------
template<int CIN,int COUT,int S,int K,int SP,int WSPLIT,int BDIM,int MINB>
__global__ __launch_bounds__(BDIM, MINB)
void conv4d_fullz_bp(const float* __restrict__ in, const float* __restrict__ wt,
                     const float* __restrict__ bias, float* __restrict__ out)
{
    constexpr int O    = S - K + 1;
    constexpr int K4   = K * K * K * K;
    constexpr int OWT  = O / WSPLIT;
    constexpr int WT   = OWT + K - 1;
    static_assert(O % WSPLIT == 0 && BDIM >= OWT * O * O, "");
    static_assert(SP >= S && SP % 2 == 0 && (S * SP) % 2 == 0, "");
    constexpr int ISZ = WT * S * S * SP;    // u64 per cin chunk
    constexpr int WCH = COUT * K4;
    static_assert(WCH % 2 == 0 && (K * COUT) % 2 == 0, "");

    extern __shared__ u64 smu[];
    u64* sw2 = smu;
    u64* siu = smu + WCH;

    const int tid = threadIdx.x;
    const int ws  = blockIdx.x % WSPLIT;
    const int bp  = blockIdx.x / WSPLIT;
    const int w0  = ws * OWT;

    const int pos = tid;
    int oy = pos % O, t0 = pos / O;
    int ox = t0 % O, owl = t0 / O;
    const bool active = (pos < OWT * O * O);

    u64 acc[COUT][O];
    #pragma unroll
    for (int c = 0; c < COUT; c++) {
        float bv = bias[c];
        u64 bpk = pk2(bv, bv);
        #pragma unroll
        for (int z = 0; z < O; z++) acc[c][z] = bpk;
    }

    const float* inb0 = in + (size_t)(2*bp)     * CIN * S * S * S * S;
    const float* inb1 = in + (size_t)(2*bp + 1) * CIN * S * S * S * S;

    for (int cin = 0; cin < CIN; cin++) {
        __syncthreads();
        for (int i = tid; i < WCH; i += BDIM) {
            int c = i / K4;
            int r = i - c * K4;
            float w = wt[(c * CIN + cin) * K4 + r];
            sw2[r * COUT + c] = pk2(w, w);
        }
        #pragma unroll 2
        for (int i = tid; i < ISZ; i += BDIM) {
            int zz = i % SP; int t = i / SP;
            int yy = t % S;  t /= S;
            int xx = t % S;  int wl = t / S;
            float v0 = 0.f, v1 = 0.f;
            if (zz < S) {
                size_t gidx = ((((size_t)cin * S + (w0 + wl)) * S + xx) * S + yy) * S + zz;
                v0 = inb0[gidx];
                v1 = inb1[gidx];
            }
            siu[i] = pk2(v0, v1);
        }
        __syncthreads();

        if (active) {
            #pragma unroll 1
            for (int kw = 0; kw < K; kw++)
            #pragma unroll 1
            for (int kx = 0; kx < K; kx++) {
                const u64* plane = siu + ((owl + kw) * S + ox + kx) * S * SP;
                const u64* wb = sw2 + ((kw * K + kx) * K * K) * COUT;
                #pragma unroll
                for (int ky = 0; ky < K; ky++) {
                    u64 wr[K * COUT];
                    const ulonglong2* w2p =
                        reinterpret_cast<const ulonglong2*>(wb + ky * K * COUT);
                    #pragma unroll
                    for (int i = 0; i < K * COUT / 2; i++) {
                        ulonglong2 v = w2p[i];
                        wr[2*i] = v.x; wr[2*i+1] = v.y;
                    }
                    u64 row[SP];
                    const ulonglong2* r2p =
                        reinterpret_cast<const ulonglong2*>(plane + (oy + ky) * SP);
                    #pragma unroll
                    for (int i = 0; i < SP / 2; i++) {
                        ulonglong2 v = r2p[i];
                        row[2*i] = v.x; row[2*i+1] = v.y;
                    }
                    #pragma unroll
                    for (int kz = 0; kz < K; kz++)
                    #pragma unroll
                    for (int z = 0; z < O; z++)
                    #pragma unroll
                    for (int c = 0; c < COUT; c++)
                        acc[c][z] = fma2(row[z + kz], wr[kz*COUT + c], acc[c][z]);
                }
            }
        }
    }

    if (active) {
        const int ow = w0 + owl;
        float* outb0 = out + (size_t)(2*bp)     * COUT * O * O * O * O;
        float* outb1 = out + (size_t)(2*bp + 1) * COUT * O * O * O * O;
        #pragma unroll
        for (int c = 0; c < COUT; c++)
        #pragma unroll
        for (int z = 0; z < O; z++) {
            float lo, hi; unpk2(acc[c][z], lo, hi);
            size_t idx = (((size_t)(c * O + ow) * O + ox) * O + oy) * O + z;
            outb0[idx] = fmaxf(lo, 0.f);
            outb1[idx] = fmaxf(hi, 0.f);
        }
    }
}

// ---------------------------------------------------------------------------
// Tiny last conv: thread = one (ow,ox,oy,oz) point, all COUT channels (scalar).
// ---------------------------------------------------------------------------
template<int CIN,int COUT,int S,int K,int BDIM>
__global__ __launch_bounds__(BDIM)
void conv4d_point(const float* __restrict__ in, const float* __restrict__ wt,
                  const float* __restrict__ bias, float* __restrict__ out)
{
    constexpr int O   = S - K + 1;
    constexpr int ISZ = CIN * S * S * S * S;
    constexpr int WSZ = COUT * CIN * K * K * K * K;
    extern __shared__ float sm[];
    float* si = sm; float* sw = sm + ISZ;
    const int tid = threadIdx.x, b = blockIdx.x;

    for (int i = tid; i < WSZ; i += BDIM) {
        int c = i / (CIN*K*K*K*K); int r = i - c * (CIN*K*K*K*K);
        sw[r * COUT + c] = wt[i];
    }
    const float* inb = in + (size_t)b * ISZ;
    for (int i = tid; i < ISZ; i += BDIM) si[i] = inb[i];
    __syncthreads();

    for (int pos = tid; pos < O * O * O * O; pos += BDIM) {
        int oz = pos % O; int t = pos / O;
        int oy = t % O;   t /= O;
        int ox = t % O;   int ow = t / O;

        float acc[COUT];
        #pragma unroll
        for (int c = 0; c < COUT; c++) acc[c] = bias[c];

        #pragma unroll 1
        for (int cin = 0; cin < CIN; cin++)
        #pragma unroll 1
        for (int kw = 0; kw < K; kw++)
        #pragma unroll 1
        for (int kx = 0; kx < K; kx++) {
            const float* plane = si + ((cin * S + ow + kw) * S + ox + kx) * S * S;
            #pragma unroll
            for (int ky = 0; ky < K; ky++) {
                const float* r  = plane + (oy + ky) * S + oz;
                const float* wp = sw + ((((cin*K + kw)*K + kx)*K + ky) * K) * COUT;
                #pragma unroll
                for (int kz = 0; kz < K; kz++)
                #pragma unroll
                for (int c = 0; c < COUT; c++)
                    acc[c] = fmaf(r[kz], wp[kz * COUT + c], acc[c]);
            }
        }
        float* outb = out + (size_t)b * COUT * O * O * O * O;
        #pragma unroll
        for (int c = 0; c < COUT; c++)
            outb[(((c * O + ow) * O + ox) * O + oy) * O + oz] = fmaxf(acc[c], 0.f);
    }
}

// ---------------------------------------------------------------------------
// Fused dense1(relu) + dense2 + softmax. One block per batch row.
// ---------------------------------------------------------------------------
__global__ __launch_bounds__(256)
void dense_head(const float* __restrict__ h, const float* __restrict__ dw1,
                const float* __restrict__ db1, const float* __restrict__ dw2,
                const float* __restrict__ db2, float* __restrict__ out)
{
    __shared__ float srow[1280];
    __shared__ float g[33];
    const int b = blockIdx.x, tid = threadIdx.x;

    for (int i = tid; i < 1280; i += 256) srow[i] = h[b * 1280 + i];
    __syncthreads();

    const int f = tid >> 2, p = tid & 3;
    float s = 0.f;
    if (f < 33) {
        const float* wrow = dw1 + f * 1280;
        for (int k = p; k < 1280; k += 4) s = fmaf(srow[k], wrow[k], s);
    }
    s += __shfl_xor_sync(0xffffffffu, s, 1);
    s += __shfl_xor_sync(0xffffffffu, s, 2);
    if (p == 0 && f < 33) g[f] = fmaxf(s + db1[f], 0.f);
    __syncthreads();

    if (tid == 0) {
        float l0 = db2[0], l1 = db2[1];
        #pragma unroll
        for (int j = 0; j < 33; j++) {
            l0 = fmaf(g[j], dw2[j], l0);
            l1 = fmaf(g[j], dw2[33 + j], l1);
        }
        float m  = fmaxf(l0, l1);
        float e0 = expf(l0 - m), e1 = expf(l1 - m);
        float inv = 1.f / (e0 + e1);
        out[b * 2 + 0] = e0 * inv;
        out[b * 2 + 1] = e1 * inv;
    }
}

// ---------------------------------------------------------------------------
extern "C" void kernel_launch(void* const* d_in, const int* in_sizes, int n_in,
                              void* d_out, int out_size)
{
    (void)in_sizes; (void)n_in; (void)out_size;
    const float* x   = (const float*)d_in[0];
    const float* w1  = (const float*)d_in[1];  const float* b1  = (const float*)d_in[2];
    const float* w2  = (const float*)d_in[3];  const float* b2  = (const float*)d_in[4];
    const float* w3  = (const float*)d_in[5];  const float* b3  = (const float*)d_in[6];
    const float* w4  = (const float*)d_in[7];  const float* b4  = (const float*)d_in[8];
    const float* w5  = (const float*)d_in[9];  const float* b5  = (const float*)d_in[10];
    const float* dw1 = (const float*)d_in[11]; const float* db1 = (const float*)d_in[12];
    const float* dw2 = (const float*)d_in[13]; const float* db2 = (const float*)d_in[14];
    float* out = (float*)d_out;

    void *p1, *p2, *p3, *p4, *p5;
    cudaGetSymbolAddress(&p1, g_h1);
    cudaGetSymbolAddress(&p2, g_h2);
    cudaGetSymbolAddress(&p3, g_h3);
    cudaGetSymbolAddress(&p4, g_h4);
    cudaGetSymbolAddress(&p5, g_h5);
    float *h1 = (float*)p1, *h2 = (float*)p2, *h3 = (float*)p3,
          *h4 = (float*)p4, *h5 = (float*)p5;

    // smem (u64 entries * 8 bytes): per-cin weights + padded input window
    constexpr int SM1 = (3*256 + 18*18*4*8) * 8;   // (768+10368)*8  =  89.1 KB -> 2 CTAs
    constexpr int SM2 = (3*256 + 15*15*4*8) * 8;   // (768+7200)*8   =  63.7 KB -> 3 CTAs
    constexpr int SM3 = (4*256 + 12*12*4*6) * 8;   // (1024+3456)*8  =  35.8 KB -> 5 CTAs
    constexpr int SM4 = (5*256 + 5*9*9*10)  * 8;   // (1280+4050)*8  =  42.6 KB -> 4 CTAs
    constexpr int SM5 = (5*6*6*6*6 + 5*5*81) * 4;  //  34.0 KB

    // L1: S=18,K=4, TZ=5 (NTZ=3 exact), TZIP=8, BDIM=256
    cudaFuncSetAttribute((const void*)conv4d_t1_bp<1,3,18,4,5,8,256,2>,
                         cudaFuncAttributeMaxDynamicSharedMemorySize, SM1);
    // L2: S=15,K=4, TZ=4 (NTZ=3 exact), TZIP=8, BDIM=160
    cudaFuncSetAttribute((const void*)conv4d_t1_bp<3,3,15,4,4,8,160,3>,
                         cudaFuncAttributeMaxDynamicSharedMemorySize, SM2);
    // L3: S=12,K=4, TZ=3 (NTZ=3 exact), TZIP=6, BDIM=96
    cudaFuncSetAttribute((const void*)conv4d_t1_bp<3,4,12,4,3,6,96,5>,
                         cudaFuncAttributeMaxDynamicSharedMemorySize, SM3);
    // L4: S=9,K=4, SP=10, WSPLIT=3 (OWT=2), BDIM=96
    cudaFuncSetAttribute((const void*)conv4d_fullz_bp<4,5,9,4,10,3,96,4>,
                         cudaFuncAttributeMaxDynamicSharedMemorySize, SM4);
    cudaFuncSetAttribute((const void*)conv4d_point<5,5,6,3,256>,
                         cudaFuncAttributeMaxDynamicSharedMemorySize, SM5);

    constexpr int NBP = BATCH / 2;   // 128 batch pairs

    conv4d_t1_bp<1,3,18,4,5,8,256,2><<<NBP*15*3, 256, SM1>>>(x,  w1, b1, h1);
    conv4d_t1_bp<3,3,15,4,4,8,160,3><<<NBP*12*3, 160, SM2>>>(h1, w2, b2, h2);
    conv4d_t1_bp<3,4,12,4,3,6,96,5><<<NBP*9*3,   96, SM3>>>(h2, w3, b3, h3);
    conv4d_fullz_bp<4,5,9,4,10,3,96,4><<<NBP*3,  96, SM4>>>(h3, w4, b4, h4);
    conv4d_point<5,5,6,3,256><<<BATCH, 256, SM5>>>(h4, w5, b5, h5);
    dense_head<<<BATCH, 256>>>(h5, dw1, db1, dw2, db2, out);
}

// round 6
// speedup vs baseline: 1.9610x; 1.9610x over previous
#include <cuda_runtime.h>

#define BATCH 256

// ---------------- intermediate scratch (device globals; no allocs) ----------
__device__ float g_h1[BATCH*3*15*15*15*15];   // 155.5 MB
__device__ float g_h2[BATCH*3*12*12*12*12];   //  63.7 MB
__device__ float g_h3[BATCH*4*9*9*9*9];       //  26.9 MB
__device__ float g_h4[BATCH*5*6*6*6*6];       //   6.6 MB
__device__ float g_h5[BATCH*5*4*4*4*4];       //   1.3 MB

typedef unsigned long long u64;

__device__ __forceinline__ u64 pk2(float lo, float hi) {
    u64 d; asm("mov.b64 %0, {%1, %2};" : "=l"(d) : "f"(lo), "f"(hi)); return d;
}
__device__ __forceinline__ void unpk2(u64 v, float& lo, float& hi) {
    asm("mov.b64 {%0, %1}, %2;" : "=f"(lo), "=f"(hi) : "l"(v));
}
__device__ __forceinline__ u64 fma2(u64 a, u64 b, u64 c) {
    u64 d; asm("fma.rn.f32x2 %0, %1, %2, %3;" : "=l"(d) : "l"(a), "l"(b), "l"(c));
    return d;
}

// ---------------------------------------------------------------------------
// Batch-paired 4D conv, FFMA2 over two batch images, big register tiles.
// Input staged per-(ww,xx) slab of SLAB u64 (SLAB odd -> conflict-free LDS.64
// across the ox lane dimension). Exact y/z tiling (no guards). Weights staged
// per-cin as duplicated u64 pairs (broadcast hoists).
// ---------------------------------------------------------------------------
template<int CIN,int COUT,int S,int K,int TY,int TZ,int SLAB,int BDIM,int MINB>
__global__ __launch_bounds__(BDIM, MINB)
void conv4d_yz_bp(const float* __restrict__ in, const float* __restrict__ wt,
                  const float* __restrict__ bias, float* __restrict__ out)
{
    constexpr int O   = S - K + 1;
    static_assert(O % TY == 0 && O % TZ == 0, "exact tiling");
    static_assert(BDIM >= O * O, "one pos per thread");
    constexpr int NTY = O / TY, NTZ = O / TZ;
    constexpr int TYI = TY + K - 1, TZI = TZ + K - 1;
    static_assert(SLAB >= TYI * TZI && SLAB % 2 == 1, "odd slab stride");
    constexpr int K4  = K * K * K * K;
    constexpr int ISZ = S * S * SLAB;       // u64 entries per cin
    constexpr int WCH = COUT * K4;          // u64 entries per cin

    extern __shared__ u64 smu[];
    u64* sw2 = smu;            // weight pairs for current cin
    u64* siu = smu + WCH;      // batch-interleaved input slabs

    const int tid = threadIdx.x;
    int bid = blockIdx.x;
    const int tzb = bid % NTZ; bid /= NTZ;
    const int tyb = bid % NTY;
    const int bp  = bid / NTY;
    const int y0 = tyb * TY, z0 = tzb * TZ;

    const int pos = tid;
    const int ow  = pos / O, ox = pos - ow * O;
    const bool active = (pos < O * O);

    u64 acc[COUT][TY][TZ];
    #pragma unroll
    for (int c = 0; c < COUT; c++) {
        float bv = bias[c];
        u64 bpk = pk2(bv, bv);
        #pragma unroll
        for (int ty = 0; ty < TY; ty++)
            #pragma unroll
            for (int tz = 0; tz < TZ; tz++) acc[c][ty][tz] = bpk;
    }

    const float* inb0 = in + (size_t)(2*bp)     * CIN * S * S * S * S;
    const float* inb1 = in + (size_t)(2*bp + 1) * CIN * S * S * S * S;

    for (int cin = 0; cin < CIN; cin++) {
        __syncthreads();
        // weights: gmem [c][cin][k4] -> smem [k4][c] dup pairs
        for (int i = tid; i < WCH; i += BDIM) {
            int c = i / K4;
            int r = i - c * K4;
            float w = wt[(c * CIN + cin) * K4 + r];
            sw2[r * COUT + c] = pk2(w, w);
        }
        // input slabs: [ww][xx][slab: iy*TZI+zz, pad]
        for (int i = tid; i < ISZ; i += BDIM) {
            int s = i % SLAB; int t = i / SLAB;
            int xx = t % S;   int ww = t / S;
            float v0 = 0.f, v1 = 0.f;
            if (s < TYI * TZI) {
                int iy = s / TZI, zz = s - iy * TZI;
                size_t gidx = ((((size_t)cin * S + ww) * S + xx) * S + (y0 + iy)) * S
                              + (z0 + zz);
                v0 = inb0[gidx];
                v1 = inb1[gidx];
            }
            siu[i] = pk2(v0, v1);
        }
        __syncthreads();

        if (active) {
            #pragma unroll 1
            for (int kw = 0; kw < K; kw++)
            #pragma unroll 1
            for (int kx = 0; kx < K; kx++) {
                const u64* ip = siu + ((ow + kw) * S + ox + kx) * SLAB;
                const u64* wb = sw2 + ((kw * K + kx) * K * K) * COUT;
                #pragma unroll
                for (int ky = 0; ky < K; ky++) {
                    u64 wr[K * COUT];                 // broadcast hoist
                    #pragma unroll
                    for (int i = 0; i < K * COUT; i++) wr[i] = wb[ky * K * COUT + i];
                    #pragma unroll
                    for (int ty = 0; ty < TY; ty++) {
                        const u64* rp0 = ip + (ky + ty) * TZI;
                        u64 row[TZI];
                        #pragma unroll
                        for (int z = 0; z < TZI; z++) row[z] = rp0[z];
                        #pragma unroll
                        for (int kz = 0; kz < K; kz++)
                        #pragma unroll
                        for (int tz = 0; tz < TZ; tz++)
                        #pragma unroll
                        for (int c = 0; c < COUT; c++)
                            acc[c][ty][tz] = fma2(row[tz + kz], wr[kz*COUT + c],
                                                  acc[c][ty][tz]);
                    }
                }
            }
        }
    }

    if (active) {
        float* outb0 = out + (size_t)(2*bp)     * COUT * O * O * O * O;
        float* outb1 = out + (size_t)(2*bp + 1) * COUT * O * O * O * O;
        #pragma unroll
        for (int c = 0; c < COUT; c++)
        #pragma unroll
        for (int ty = 0; ty < TY; ty++)
        #pragma unroll
        for (int tz = 0; tz < TZ; tz++) {
            float lo, hi; unpk2(acc[c][ty][tz], lo, hi);
            size_t idx = (((size_t)(c * O + ow) * O + ox) * O + (y0 + ty)) * O
                         + (z0 + tz);
            outb0[idx] = fmaxf(lo, 0.f);
            outb1[idx] = fmaxf(hi, 0.f);
        }
    }
}

// ---------------------------------------------------------------------------
// Batch-paired whole-spatial conv (L4), W-split. Thread = (owl,ox,oy),
// full-Z u64 accumulators. All lane strides odd (S=9, S*S=81).
// ---------------------------------------------------------------------------
template<int CIN,int COUT,int S,int K,int WSPLIT,int BDIM,int MINB>
__global__ __launch_bounds__(BDIM, MINB)
void conv4d_fullz_bp(const float* __restrict__ in, const float* __restrict__ wt,
                     const float* __restrict__ bias, float* __restrict__ out)
{
    constexpr int O    = S - K + 1;
    constexpr int K4   = K * K * K * K;
    constexpr int OWT  = O / WSPLIT;
    constexpr int WT   = OWT + K - 1;
    static_assert(O % WSPLIT == 0 && BDIM >= OWT * O * O, "");
    constexpr int ISZ = WT * S * S * S;
    constexpr int WCH = COUT * K4;

    extern __shared__ u64 smu[];
    u64* sw2 = smu;
    u64* siu = smu + WCH;

    const int tid = threadIdx.x;
    const int ws  = blockIdx.x % WSPLIT;
    const int bp  = blockIdx.x / WSPLIT;
    const int w0  = ws * OWT;

    const int pos = tid;
    int oy = pos % O, t0 = pos / O;
    int ox = t0 % O, owl = t0 / O;
    const bool active = (pos < OWT * O * O);

    u64 acc[COUT][O];
    #pragma unroll
    for (int c = 0; c < COUT; c++) {
        float bv = bias[c];
        u64 bpk = pk2(bv, bv);
        #pragma unroll
        for (int z = 0; z < O; z++) acc[c][z] = bpk;
    }

    const float* inb0 = in + (size_t)(2*bp)     * CIN * S * S * S * S;
    const float* inb1 = in + (size_t)(2*bp + 1) * CIN * S * S * S * S;

    for (int cin = 0; cin < CIN; cin++) {
        __syncthreads();
        for (int i = tid; i < WCH; i += BDIM) {
            int c = i / K4;
            int r = i - c * K4;
            float w = wt[(c * CIN + cin) * K4 + r];
            sw2[r * COUT + c] = pk2(w, w);
        }
        for (int i = tid; i < ISZ; i += BDIM) {
            int zz = i % S; int t = i / S;
            int yy = t % S; t /= S;
            int xx = t % S; int wl = t / S;
            size_t gidx = ((((size_t)cin * S + (w0 + wl)) * S + xx) * S + yy) * S + zz;
            siu[i] = pk2(inb0[gidx], inb1[gidx]);
        }
        __syncthreads();

        if (active) {
            #pragma unroll 1
            for (int kw = 0; kw < K; kw++)
            #pragma unroll 1
            for (int kx = 0; kx < K; kx++) {
                const u64* plane = siu + ((owl + kw) * S + ox + kx) * S * S;
                const u64* wb = sw2 + ((kw * K + kx) * K * K) * COUT;
                #pragma unroll
                for (int ky = 0; ky < K; ky++) {
                    u64 wr[K * COUT];
                    #pragma unroll
                    for (int i = 0; i < K * COUT; i++) wr[i] = wb[ky * K * COUT + i];
                    const u64* rowp = plane + (oy + ky) * S;
                    u64 row[S];
                    #pragma unroll
                    for (int z = 0; z < S; z++) row[z] = rowp[z];
                    #pragma unroll
                    for (int kz = 0; kz < K; kz++)
                    #pragma unroll
                    for (int z = 0; z < O; z++)
                    #pragma unroll
                    for (int c = 0; c < COUT; c++)
                        acc[c][z] = fma2(row[z + kz], wr[kz*COUT + c], acc[c][z]);
                }
            }
        }
    }

    if (active) {
        const int ow = w0 + owl;
        float* outb0 = out + (size_t)(2*bp)     * COUT * O * O * O * O;
        float* outb1 = out + (size_t)(2*bp + 1) * COUT * O * O * O * O;
        #pragma unroll
        for (int c = 0; c < COUT; c++)
        #pragma unroll
        for (int z = 0; z < O; z++) {
            float lo, hi; unpk2(acc[c][z], lo, hi);
            size_t idx = (((size_t)(c * O + ow) * O + ox) * O + oy) * O + z;
            outb0[idx] = fmaxf(lo, 0.f);
            outb1[idx] = fmaxf(hi, 0.f);
        }
    }
}

// ---------------------------------------------------------------------------
// Tiny last conv: thread = one (ow,ox,oy,oz) point, all COUT channels (scalar).
// ---------------------------------------------------------------------------
template<int CIN,int COUT,int S,int K,int BDIM>
__global__ __launch_bounds__(BDIM)
void conv4d_point(const float* __restrict__ in, const float* __restrict__ wt,
                  const float* __restrict__ bias, float* __restrict__ out)
{
    constexpr int O   = S - K + 1;
    constexpr int ISZ = CIN * S * S * S * S;
    constexpr int WSZ = COUT * CIN * K * K * K * K;
    extern __shared__ float sm[];
    float* si = sm; float* sw = sm + ISZ;
    const int tid = threadIdx.x, b = blockIdx.x;

    for (int i = tid; i < WSZ; i += BDIM) {
        int c = i / (CIN*K*K*K*K); int r = i - c * (CIN*K*K*K*K);
        sw[r * COUT + c] = wt[i];
    }
    const float* inb = in + (size_t)b * ISZ;
    for (int i = tid; i < ISZ; i += BDIM) si[i] = inb[i];
    __syncthreads();

    for (int pos = tid; pos < O * O * O * O; pos += BDIM) {
        int oz = pos % O; int t = pos / O;
        int oy = t % O;   t /= O;
        int ox = t % O;   int ow = t / O;

        float acc[COUT];
        #pragma unroll
        for (int c = 0; c < COUT; c++) acc[c] = bias[c];

        #pragma unroll 1
        for (int cin = 0; cin < CIN; cin++)
        #pragma unroll 1
        for (int kw = 0; kw < K; kw++)
        #pragma unroll 1
        for (int kx = 0; kx < K; kx++) {
            const float* plane = si + ((cin * S + ow + kw) * S + ox + kx) * S * S;
            #pragma unroll
            for (int ky = 0; ky < K; ky++) {
                const float* r  = plane + (oy + ky) * S + oz;
                const float* wp = sw + ((((cin*K + kw)*K + kx)*K + ky) * K) * COUT;
                #pragma unroll
                for (int kz = 0; kz < K; kz++)
                #pragma unroll
                for (int c = 0; c < COUT; c++)
                    acc[c] = fmaf(r[kz], wp[kz * COUT + c], acc[c]);
            }
        }
        float* outb = out + (size_t)b * COUT * O * O * O * O;
        #pragma unroll
        for (int c = 0; c < COUT; c++)
            outb[(((c * O + ow) * O + ox) * O + oy) * O + oz] = fmaxf(acc[c], 0.f);
    }
}

// ---------------------------------------------------------------------------
// Fused dense1(relu) + dense2 + softmax. One block per batch row.
// ---------------------------------------------------------------------------
__global__ __launch_bounds__(256)
void dense_head(const float* __restrict__ h, const float* __restrict__ dw1,
                const float* __restrict__ db1, const float* __restrict__ dw2,
                const float* __restrict__ db2, float* __restrict__ out)
{
    __shared__ float srow[1280];
    __shared__ float g[33];
    const int b = blockIdx.x, tid = threadIdx.x;

    for (int i = tid; i < 1280; i += 256) srow[i] = h[b * 1280 + i];
    __syncthreads();

    const int f = tid >> 2, p = tid & 3;
    float s = 0.f;
    if (f < 33) {
        const float* wrow = dw1 + f * 1280;
        for (int k = p; k < 1280; k += 4) s = fmaf(srow[k], wrow[k], s);
    }
    s += __shfl_xor_sync(0xffffffffu, s, 1);
    s += __shfl_xor_sync(0xffffffffu, s, 2);
    if (p == 0 && f < 33) g[f] = fmaxf(s + db1[f], 0.f);
    __syncthreads();

    if (tid == 0) {
        float l0 = db2[0], l1 = db2[1];
        #pragma unroll
        for (int j = 0; j < 33; j++) {
            l0 = fmaf(g[j], dw2[j], l0);
            l1 = fmaf(g[j], dw2[33 + j], l1);
        }
        float m  = fmaxf(l0, l1);
        float e0 = expf(l0 - m), e1 = expf(l1 - m);
        float inv = 1.f / (e0 + e1);
        out[b * 2 + 0] = e0 * inv;
        out[b * 2 + 1] = e1 * inv;
    }
}

// ---------------------------------------------------------------------------
extern "C" void kernel_launch(void* const* d_in, const int* in_sizes, int n_in,
                              void* d_out, int out_size)
{
    (void)in_sizes; (void)n_in; (void)out_size;
    const float* x   = (const float*)d_in[0];
    const float* w1  = (const float*)d_in[1];  const float* b1  = (const float*)d_in[2];
    const float* w2  = (const float*)d_in[3];  const float* b2  = (const float*)d_in[4];
    const float* w3  = (const float*)d_in[5];  const float* b3  = (const float*)d_in[6];
    const float* w4  = (const float*)d_in[7];  const float* b4  = (const float*)d_in[8];
    const float* w5  = (const float*)d_in[9];  const float* b5  = (const float*)d_in[10];
    const float* dw1 = (const float*)d_in[11]; const float* db1 = (const float*)d_in[12];
    const float* dw2 = (const float*)d_in[13]; const float* db2 = (const float*)d_in[14];
    float* out = (float*)d_out;

    void *p1, *p2, *p3, *p4, *p5;
    cudaGetSymbolAddress(&p1, g_h1);
    cudaGetSymbolAddress(&p2, g_h2);
    cudaGetSymbolAddress(&p3, g_h3);
    cudaGetSymbolAddress(&p4, g_h4);
    cudaGetSymbolAddress(&p5, g_h5);
    float *h1 = (float*)p1, *h2 = (float*)p2, *h3 = (float*)p3,
          *h4 = (float*)p4, *h5 = (float*)p5;

    // smem (u64 * 8B): per-cin weight pairs + slab-padded input pairs
    constexpr int SM1 = (3*256 + 18*18*37) * 8;   // 102,048 -> 2 CTAs
    constexpr int SM2 = (3*256 + 15*15*49) * 8;   //  94,344 -> 2 CTAs
    constexpr int SM3 = (4*256 + 12*12*37) * 8;   //  50,816 -> 4 CTAs
    constexpr int SM4 = (5*256 + 5*9*9*9)  * 8;   //  39,400 -> 4 CTAs (regs)
    constexpr int SM5 = (5*6*6*6*6 + 5*5*81) * 4; //  34.0 KB

    // L1: TY=3,TZ=3 (NTY=NTZ=5), SLAB=37 (odd), BDIM=256
    cudaFuncSetAttribute((const void*)conv4d_yz_bp<1,3,18,4,3,3,37,256,2>,
                         cudaFuncAttributeMaxDynamicSharedMemorySize, SM1);
    // L2: TY=4,TZ=4 (NTY=NTZ=3), SLAB=49 (odd), BDIM=160 (ratio 4.8 -> fma-bound)
    cudaFuncSetAttribute((const void*)conv4d_yz_bp<3,3,15,4,4,4,49,160,2>,
                         cudaFuncAttributeMaxDynamicSharedMemorySize, SM2);
    // L3: TY=3,TZ=3 (NTY=NTZ=3), SLAB=37 (odd; was 36 -> 8-way conflicts), BDIM=96
    cudaFuncSetAttribute((const void*)conv4d_yz_bp<3,4,12,4,3,3,37,96,4>,
                         cudaFuncAttributeMaxDynamicSharedMemorySize, SM3);
    // L4: WSPLIT=3 (OWT=2, grid 384), BDIM=96
    cudaFuncSetAttribute((const void*)conv4d_fullz_bp<4,5,9,4,3,96,4>,
                         cudaFuncAttributeMaxDynamicSharedMemorySize, SM4);
    cudaFuncSetAttribute((const void*)conv4d_point<5,5,6,3,256>,
                         cudaFuncAttributeMaxDynamicSharedMemorySize, SM5);

    constexpr int NBP = BATCH / 2;   // 128 batch pairs

    conv4d_yz_bp<1,3,18,4,3,3,37,256,2><<<NBP*5*5, 256, SM1>>>(x,  w1, b1, h1);
    conv4d_yz_bp<3,3,15,4,4,4,49,160,2><<<NBP*3*3, 160, SM2>>>(h1, w2, b2, h2);
    conv4d_yz_bp<3,4,12,4,3,3,37,96,4><<<NBP*3*3,  96, SM3>>>(h2, w3, b3, h3);
    conv4d_fullz_bp<4,5,9,4,3,96,4><<<NBP*3, 96, SM4>>>(h3, w4, b4, h4);
    conv4d_point<5,5,6,3,256><<<BATCH, 256, SM5>>>(h4, w5, b5, h5);
    dense_head<<<BATCH, 256>>>(h5, dw1, db1, dw2, db2, out);
}

// round 7
// speedup vs baseline: 2.0869x; 1.0642x over previous
#include <cuda_runtime.h>

#define BATCH 256

// ---------------- intermediate scratch (device globals; no allocs) ----------
__device__ float g_h1[BATCH*3*15*15*15*15];   // 155.5 MB
__device__ float g_h2[BATCH*3*12*12*12*12];   //  63.7 MB
__device__ float g_h3[BATCH*4*9*9*9*9];       //  26.9 MB
__device__ float g_h4[BATCH*5*6*6*6*6];       //   6.6 MB
__device__ float g_h5[BATCH*5*4*4*4*4];       //   1.3 MB

typedef unsigned long long u64;

__device__ __forceinline__ u64 pk2(float lo, float hi) {
    u64 d; asm("mov.b64 %0, {%1, %2};" : "=l"(d) : "f"(lo), "f"(hi)); return d;
}
__device__ __forceinline__ void unpk2(u64 v, float& lo, float& hi) {
    asm("mov.b64 {%0, %1}, %2;" : "=f"(lo), "=f"(hi) : "l"(v));
}
__device__ __forceinline__ u64 fma2(u64 a, u64 b, u64 c) {
    u64 d; asm("fma.rn.f32x2 %0, %1, %2, %3;" : "=l"(d) : "l"(a), "l"(b), "l"(c));
    return d;
}

// ---------------------------------------------------------------------------
// Batch-paired conv, streaming rows (used for L1). Odd SLAB stride.
// ---------------------------------------------------------------------------
template<int CIN,int COUT,int S,int K,int TY,int TZ,int SLAB,int BDIM,int MINB>
__global__ __launch_bounds__(BDIM, MINB)
void conv4d_yz_bp(const float* __restrict__ in, const float* __restrict__ wt,
                  const float* __restrict__ bias, float* __restrict__ out)
{
    constexpr int O   = S - K + 1;
    static_assert(O % TY == 0 && O % TZ == 0, "exact tiling");
    static_assert(BDIM >= O * O, "one pos per thread");
    constexpr int NTY = O / TY, NTZ = O / TZ;
    constexpr int TYI = TY + K - 1, TZI = TZ + K - 1;
    static_assert(SLAB >= TYI * TZI && SLAB % 2 == 1, "odd slab stride");
    constexpr int K4  = K * K * K * K;
    constexpr int ISZ = S * S * SLAB;
    constexpr int WCH = COUT * K4;

    extern __shared__ u64 smu[];
    u64* sw2 = smu;
    u64* siu = smu + WCH;

    const int tid = threadIdx.x;
    int bid = blockIdx.x;
    const int tzb = bid % NTZ; bid /= NTZ;
    const int tyb = bid % NTY;
    const int bp  = bid / NTY;
    const int y0 = tyb * TY, z0 = tzb * TZ;

    const int pos = tid;
    const int ow  = pos / O, ox = pos - ow * O;
    const bool active = (pos < O * O);

    u64 acc[COUT][TY][TZ];
    #pragma unroll
    for (int c = 0; c < COUT; c++) {
        float bv = bias[c];
        u64 bpk = pk2(bv, bv);
        #pragma unroll
        for (int ty = 0; ty < TY; ty++)
            #pragma unroll
            for (int tz = 0; tz < TZ; tz++) acc[c][ty][tz] = bpk;
    }

    const float* inb0 = in + (size_t)(2*bp)     * CIN * S * S * S * S;
    const float* inb1 = in + (size_t)(2*bp + 1) * CIN * S * S * S * S;

    for (int cin = 0; cin < CIN; cin++) {
        __syncthreads();
        for (int i = tid; i < WCH; i += BDIM) {
            int c = i / K4;
            int r = i - c * K4;
            float w = wt[(c * CIN + cin) * K4 + r];
            sw2[r * COUT + c] = pk2(w, w);
        }
        for (int i = tid; i < ISZ; i += BDIM) {
            int s = i % SLAB; int t = i / SLAB;
            int xx = t % S;   int ww = t / S;
            float v0 = 0.f, v1 = 0.f;
            if (s < TYI * TZI) {
                int iy = s / TZI, zz = s - iy * TZI;
                size_t gidx = ((((size_t)cin * S + ww) * S + xx) * S + (y0 + iy)) * S
                              + (z0 + zz);
                v0 = inb0[gidx];
                v1 = inb1[gidx];
            }
            siu[i] = pk2(v0, v1);
        }
        __syncthreads();

        if (active) {
            #pragma unroll 1
            for (int kw = 0; kw < K; kw++)
            #pragma unroll 1
            for (int kx = 0; kx < K; kx++) {
                const u64* ip = siu + ((ow + kw) * S + ox + kx) * SLAB;
                const u64* wb = sw2 + ((kw * K + kx) * K * K) * COUT;
                #pragma unroll
                for (int ky = 0; ky < K; ky++) {
                    u64 wr[K * COUT];
                    #pragma unroll
                    for (int i = 0; i < K * COUT; i++) wr[i] = wb[ky * K * COUT + i];
                    #pragma unroll
                    for (int ty = 0; ty < TY; ty++) {
                        const u64* rp0 = ip + (ky + ty) * TZI;
                        u64 row[TZI];
                        #pragma unroll
                        for (int z = 0; z < TZI; z++) row[z] = rp0[z];
                        #pragma unroll
                        for (int kz = 0; kz < K; kz++)
                        #pragma unroll
                        for (int tz = 0; tz < TZ; tz++)
                        #pragma unroll
                        for (int c = 0; c < COUT; c++)
                            acc[c][ty][tz] = fma2(row[tz + kz], wr[kz*COUT + c],
                                                  acc[c][ty][tz]);
                    }
                }
            }
        }
    }

    if (active) {
        float* outb0 = out + (size_t)(2*bp)     * COUT * O * O * O * O;
        float* outb1 = out + (size_t)(2*bp + 1) * COUT * O * O * O * O;
        #pragma unroll
        for (int c = 0; c < COUT; c++)
        #pragma unroll
        for (int ty = 0; ty < TY; ty++)
        #pragma unroll
        for (int tz = 0; tz < TZ; tz++) {
            float lo, hi; unpk2(acc[c][ty][tz], lo, hi);
            size_t idx = (((size_t)(c * O + ow) * O + ox) * O + (y0 + ty)) * O
                         + (z0 + tz);
            outb0[idx] = fmaxf(lo, 0.f);
            outb1[idx] = fmaxf(hi, 0.f);
        }
    }
}

// ---------------------------------------------------------------------------
// Window-resident variant (L2,L3): per (kw,kx) the full TYI*TZI input window
// is loaded into registers ONCE (35-36 back-to-back LDS.64 -> high MLP, one
// latency hit), then the entire K*TY*K*TZ*COUT fma2 body runs on registers.
// ---------------------------------------------------------------------------
template<int CIN,int COUT,int S,int K,int TY,int TZ,int SLAB,int BDIM,int MINB>
__global__ __launch_bounds__(BDIM, MINB)
void conv4d_yz_win(const float* __restrict__ in, const float* __restrict__ wt,
                   const float* __restrict__ bias, float* __restrict__ out)
{
    constexpr int O   = S - K + 1;
    static_assert(O % TY == 0 && O % TZ == 0, "exact tiling");
    static_assert(BDIM >= O * O, "one pos per thread");
    constexpr int NTY = O / TY, NTZ = O / TZ;
    constexpr int TYI = TY + K - 1, TZI = TZ + K - 1;
    static_assert(SLAB >= TYI * TZI && SLAB % 2 == 1, "odd slab stride");
    constexpr int K4  = K * K * K * K;
    constexpr int ISZ = S * S * SLAB;
    constexpr int WCH = COUT * K4;

    extern __shared__ u64 smu[];
    u64* sw2 = smu;
    u64* siu = smu + WCH;

    const int tid = threadIdx.x;
    int bid = blockIdx.x;
    const int tzb = bid % NTZ; bid /= NTZ;
    const int tyb = bid % NTY;
    const int bp  = bid / NTY;
    const int y0 = tyb * TY, z0 = tzb * TZ;

    const int pos = tid;
    const int ow  = pos / O, ox = pos - ow * O;
    const bool active = (pos < O * O);

    u64 acc[COUT][TY][TZ];
    #pragma unroll
    for (int c = 0; c < COUT; c++) {
        float bv = bias[c];
        u64 bpk = pk2(bv, bv);
        #pragma unroll
        for (int ty = 0; ty < TY; ty++)
            #pragma unroll
            for (int tz = 0; tz < TZ; tz++) acc[c][ty][tz] = bpk;
    }

    const float* inb0 = in + (size_t)(2*bp)     * CIN * S * S * S * S;
    const float* inb1 = in + (size_t)(2*bp + 1) * CIN * S * S * S * S;

    for (int cin = 0; cin < CIN; cin++) {
        __syncthreads();
        for (int i = tid; i < WCH; i += BDIM) {
            int c = i / K4;
            int r = i - c * K4;
            float w = wt[(c * CIN + cin) * K4 + r];
            sw2[r * COUT + c] = pk2(w, w);
        }
        for (int i = tid; i < ISZ; i += BDIM) {
            int s = i % SLAB; int t = i / SLAB;
            int xx = t % S;   int ww = t / S;
            float v0 = 0.f, v1 = 0.f;
            if (s < TYI * TZI) {
                int iy = s / TZI, zz = s - iy * TZI;
                size_t gidx = ((((size_t)cin * S + ww) * S + xx) * S + (y0 + iy)) * S
                              + (z0 + zz);
                v0 = inb0[gidx];
                v1 = inb1[gidx];
            }
            siu[i] = pk2(v0, v1);
        }
        __syncthreads();

        if (active) {
            #pragma unroll 1
            for (int kw = 0; kw < K; kw++)
            #pragma unroll 1
            for (int kx = 0; kx < K; kx++) {
                const u64* ip = siu + ((ow + kw) * S + ox + kx) * SLAB;
                // load full window once (high MLP, amortized latency)
                u64 win[TYI * TZI];
                #pragma unroll
                for (int i = 0; i < TYI * TZI; i++) win[i] = ip[i];

                const u64* wb = sw2 + ((kw * K + kx) * K * K) * COUT;
                #pragma unroll
                for (int ky = 0; ky < K; ky++) {
                    u64 wr[K * COUT];
                    #pragma unroll
                    for (int i = 0; i < K * COUT; i++) wr[i] = wb[ky * K * COUT + i];
                    #pragma unroll
                    for (int ty = 0; ty < TY; ty++)
                    #pragma unroll
                    for (int kz = 0; kz < K; kz++)
                    #pragma unroll
                    for (int tz = 0; tz < TZ; tz++)
                    #pragma unroll
                    for (int c = 0; c < COUT; c++)
                        acc[c][ty][tz] = fma2(win[(ky + ty) * TZI + tz + kz],
                                              wr[kz*COUT + c], acc[c][ty][tz]);
                }
            }
        }
    }

    if (active) {
        float* outb0 = out + (size_t)(2*bp)     * COUT * O * O * O * O;
        float* outb1 = out + (size_t)(2*bp + 1) * COUT * O * O * O * O;
        #pragma unroll
        for (int c = 0; c < COUT; c++)
        #pragma unroll
        for (int ty = 0; ty < TY; ty++)
        #pragma unroll
        for (int tz = 0; tz < TZ; tz++) {
            float lo, hi; unpk2(acc[c][ty][tz], lo, hi);
            size_t idx = (((size_t)(c * O + ow) * O + ox) * O + (y0 + ty)) * O
                         + (z0 + tz);
            outb0[idx] = fmaxf(lo, 0.f);
            outb1[idx] = fmaxf(hi, 0.f);
        }
    }
}

// ---------------------------------------------------------------------------
// Batch-paired whole-spatial conv (L4), W-split (round-4 best config).
// ---------------------------------------------------------------------------
template<int CIN,int COUT,int S,int K,int WSPLIT,int BDIM,int MINB>
__global__ __launch_bounds__(BDIM, MINB)
void conv4d_fullz_bp(const float* __restrict__ in, const float* __restrict__ wt,
                     const float* __restrict__ bias, float* __restrict__ out)
{
    constexpr int O    = S - K + 1;
    constexpr int K4   = K * K * K * K;
    constexpr int OWT  = O / WSPLIT;
    constexpr int WT   = OWT + K - 1;
    static_assert(O % WSPLIT == 0 && BDIM >= OWT * O * O, "");
    constexpr int ISZ = WT * S * S * S;
    constexpr int WCH = COUT * K4;

    extern __shared__ u64 smu[];
    u64* sw2 = smu;
    u64* siu = smu + WCH;

    const int tid = threadIdx.x;
    const int ws  = blockIdx.x % WSPLIT;
    const int bp  = blockIdx.x / WSPLIT;
    const int w0  = ws * OWT;

    const int pos = tid;
    int oy = pos % O, t0 = pos / O;
    int ox = t0 % O, owl = t0 / O;
    const bool active = (pos < OWT * O * O);

    u64 acc[COUT][O];
    #pragma unroll
    for (int c = 0; c < COUT; c++) {
        float bv = bias[c];
        u64 bpk = pk2(bv, bv);
        #pragma unroll
        for (int z = 0; z < O; z++) acc[c][z] = bpk;
    }

    const float* inb0 = in + (size_t)(2*bp)     * CIN * S * S * S * S;
    const float* inb1 = in + (size_t)(2*bp + 1) * CIN * S * S * S * S;

    for (int cin = 0; cin < CIN; cin++) {
        __syncthreads();
        for (int i = tid; i < WCH; i += BDIM) {
            int c = i / K4;
            int r = i - c * K4;
            float w = wt[(c * CIN + cin) * K4 + r];
            sw2[r * COUT + c] = pk2(w, w);
        }
        for (int i = tid; i < ISZ; i += BDIM) {
            int zz = i % S; int t = i / S;
            int yy = t % S; t /= S;
            int xx = t % S; int wl = t / S;
            size_t gidx = ((((size_t)cin * S + (w0 + wl)) * S + xx) * S + yy) * S + zz;
            siu[i] = pk2(inb0[gidx], inb1[gidx]);
        }
        __syncthreads();

        if (active) {
            #pragma unroll 1
            for (int kw = 0; kw < K; kw++)
            #pragma unroll 1
            for (int kx = 0; kx < K; kx++) {
                const u64* plane = siu + ((owl + kw) * S + ox + kx) * S * S;
                const u64* wb = sw2 + ((kw * K + kx) * K * K) * COUT;
                #pragma unroll
                for (int ky = 0; ky < K; ky++) {
                    u64 wr[K * COUT];
                    #pragma unroll
                    for (int i = 0; i < K * COUT; i++) wr[i] = wb[ky * K * COUT + i];
                    const u64* rowp = plane + (oy + ky) * S;
                    u64 row[S];
                    #pragma unroll
                    for (int z = 0; z < S; z++) row[z] = rowp[z];
                    #pragma unroll
                    for (int kz = 0; kz < K; kz++)
                    #pragma unroll
                    for (int z = 0; z < O; z++)
                    #pragma unroll
                    for (int c = 0; c < COUT; c++)
                        acc[c][z] = fma2(row[z + kz], wr[kz*COUT + c], acc[c][z]);
                }
            }
        }
    }

    if (active) {
        const int ow = w0 + owl;
        float* outb0 = out + (size_t)(2*bp)     * COUT * O * O * O * O;
        float* outb1 = out + (size_t)(2*bp + 1) * COUT * O * O * O * O;
        #pragma unroll
        for (int c = 0; c < COUT; c++)
        #pragma unroll
        for (int z = 0; z < O; z++) {
            float lo, hi; unpk2(acc[c][z], lo, hi);
            size_t idx = (((size_t)(c * O + ow) * O + ox) * O + oy) * O + z;
            outb0[idx] = fmaxf(lo, 0.f);
            outb1[idx] = fmaxf(hi, 0.f);
        }
    }
}

// ---------------------------------------------------------------------------
// Tiny last conv: thread = one (ow,ox,oy,oz) point, all COUT channels (scalar).
// ---------------------------------------------------------------------------
template<int CIN,int COUT,int S,int K,int BDIM>
__global__ __launch_bounds__(BDIM)
void conv4d_point(const float* __restrict__ in, const float* __restrict__ wt,
                  const float* __restrict__ bias, float* __restrict__ out)
{
    constexpr int O   = S - K + 1;
    constexpr int ISZ = CIN * S * S * S * S;
    constexpr int WSZ = COUT * CIN * K * K * K * K;
    extern __shared__ float sm[];
    float* si = sm; float* sw = sm + ISZ;
    const int tid = threadIdx.x, b = blockIdx.x;

    for (int i = tid; i < WSZ; i += BDIM) {
        int c = i / (CIN*K*K*K*K); int r = i - c * (CIN*K*K*K*K);
        sw[r * COUT + c] = wt[i];
    }
    const float* inb = in + (size_t)b * ISZ;
    for (int i = tid; i < ISZ; i += BDIM) si[i] = inb[i];
    __syncthreads();

    for (int pos = tid; pos < O * O * O * O; pos += BDIM) {
        int oz = pos % O; int t = pos / O;
        int oy = t % O;   t /= O;
        int ox = t % O;   int ow = t / O;

        float acc[COUT];
        #pragma unroll
        for (int c = 0; c < COUT; c++) acc[c] = bias[c];

        #pragma unroll 1
        for (int cin = 0; cin < CIN; cin++)
        #pragma unroll 1
        for (int kw = 0; kw < K; kw++)
        #pragma unroll 1
        for (int kx = 0; kx < K; kx++) {
            const float* plane = si + ((cin * S + ow + kw) * S + ox + kx) * S * S;
            #pragma unroll
            for (int ky = 0; ky < K; ky++) {
                const float* r  = plane + (oy + ky) * S + oz;
                const float* wp = sw + ((((cin*K + kw)*K + kx)*K + ky) * K) * COUT;
                #pragma unroll
                for (int kz = 0; kz < K; kz++)
                #pragma unroll
                for (int c = 0; c < COUT; c++)
                    acc[c] = fmaf(r[kz], wp[kz * COUT + c], acc[c]);
            }
        }
        float* outb = out + (size_t)b * COUT * O * O * O * O;
        #pragma unroll
        for (int c = 0; c < COUT; c++)
            outb[(((c * O + ow) * O + ox) * O + oy) * O + oz] = fmaxf(acc[c], 0.f);
    }
}

// ---------------------------------------------------------------------------
// Fused dense1(relu) + dense2 + softmax. One block per batch row.
// ---------------------------------------------------------------------------
__global__ __launch_bounds__(256)
void dense_head(const float* __restrict__ h, const float* __restrict__ dw1,
                const float* __restrict__ db1, const float* __restrict__ dw2,
                const float* __restrict__ db2, float* __restrict__ out)
{
    __shared__ float srow[1280];
    __shared__ float g[33];
    const int b = blockIdx.x, tid = threadIdx.x;

    for (int i = tid; i < 1280; i += 256) srow[i] = h[b * 1280 + i];
    __syncthreads();

    const int f = tid >> 2, p = tid & 3;
    float s = 0.f;
    if (f < 33) {
        const float* wrow = dw1 + f * 1280;
        for (int k = p; k < 1280; k += 4) s = fmaf(srow[k], wrow[k], s);
    }
    s += __shfl_xor_sync(0xffffffffu, s, 1);
    s += __shfl_xor_sync(0xffffffffu, s, 2);
    if (p == 0 && f < 33) g[f] = fmaxf(s + db1[f], 0.f);
    __syncthreads();

    if (tid == 0) {
        float l0 = db2[0], l1 = db2[1];
        #pragma unroll
        for (int j = 0; j < 33; j++) {
            l0 = fmaf(g[j], dw2[j], l0);
            l1 = fmaf(g[j], dw2[33 + j], l1);
        }
        float m  = fmaxf(l0, l1);
        float e0 = expf(l0 - m), e1 = expf(l1 - m);
        float inv = 1.f / (e0 + e1);
        out[b * 2 + 0] = e0 * inv;
        out[b * 2 + 1] = e1 * inv;
    }
}

// ---------------------------------------------------------------------------
extern "C" void kernel_launch(void* const* d_in, const int* in_sizes, int n_in,
                              void* d_out, int out_size)
{
    (void)in_sizes; (void)n_in; (void)out_size;
    const float* x   = (const float*)d_in[0];
    const float* w1  = (const float*)d_in[1];  const float* b1  = (const float*)d_in[2];
    const float* w2  = (const float*)d_in[3];  const float* b2  = (const float*)d_in[4];
    const float* w3  = (const float*)d_in[5];  const float* b3  = (const float*)d_in[6];
    const float* w4  = (const float*)d_in[7];  const float* b4  = (const float*)d_in[8];
    const float* w5  = (const float*)d_in[9];  const float* b5  = (const float*)d_in[10];
    const float* dw1 = (const float*)d_in[11]; const float* db1 = (const float*)d_in[12];
    const float* dw2 = (const float*)d_in[13]; const float* db2 = (const float*)d_in[14];
    float* out = (float*)d_out;

    void *p1, *p2, *p3, *p4, *p5;
    cudaGetSymbolAddress(&p1, g_h1);
    cudaGetSymbolAddress(&p2, g_h2);
    cudaGetSymbolAddress(&p3, g_h3);
    cudaGetSymbolAddress(&p4, g_h4);
    cudaGetSymbolAddress(&p5, g_h5);
    float *h1 = (float*)p1, *h2 = (float*)p2, *h3 = (float*)p3,
          *h4 = (float*)p4, *h5 = (float*)p5;

    constexpr int SM1 = (3*256 + 18*18*37) * 8;   // 102,048 -> 2 CTAs
    constexpr int SM2 = (3*256 + 15*15*35) * 8;   //  69,144 -> 2 CTAs (regs)
    constexpr int SM3 = (4*256 + 12*12*37) * 8;   //  50,816 -> 3 CTAs (regs)
    constexpr int SM4 = (5*256 + 6*9*9*9)  * 8;   //  45,232 -> 3 CTAs
    constexpr int SM5 = (5*6*6*6*6 + 5*5*81) * 4; //  34.0 KB

    // L1: streaming, TY=3,TZ=3 (exact), SLAB=37, BDIM=256
    cudaFuncSetAttribute((const void*)conv4d_yz_bp<1,3,18,4,3,3,37,256,2>,
                         cudaFuncAttributeMaxDynamicSharedMemorySize, SM1);
    // L2: WINDOW-RESIDENT, TY=2,TZ=4 (exact), SLAB=35 (odd), BDIM=160
    cudaFuncSetAttribute((const void*)conv4d_yz_win<3,3,15,4,2,4,35,160,2>,
                         cudaFuncAttributeMaxDynamicSharedMemorySize, SM2);
    // L3: WINDOW-RESIDENT, TY=3,TZ=3 (exact), SLAB=37 (odd), BDIM=96
    cudaFuncSetAttribute((const void*)conv4d_yz_win<3,4,12,4,3,3,37,96,3>,
                         cudaFuncAttributeMaxDynamicSharedMemorySize, SM3);
    // L4: round-4 best config: WSPLIT=2 (OWT=3), BDIM=128
    cudaFuncSetAttribute((const void*)conv4d_fullz_bp<4,5,9,4,2,128,3>,
                         cudaFuncAttributeMaxDynamicSharedMemorySize, SM4);
    cudaFuncSetAttribute((const void*)conv4d_point<5,5,6,3,256>,
                         cudaFuncAttributeMaxDynamicSharedMemorySize, SM5);

    constexpr int NBP = BATCH / 2;   // 128 batch pairs

    conv4d_yz_bp<1,3,18,4,3,3,37,256,2><<<NBP*5*5, 256, SM1>>>(x,  w1, b1, h1);
    conv4d_yz_win<3,3,15,4,2,4,35,160,2><<<NBP*6*3, 160, SM2>>>(h1, w2, b2, h2);
    conv4d_yz_win<3,4,12,4,3,3,37,96,3><<<NBP*3*3,  96, SM3>>>(h2, w3, b3, h3);
    conv4d_fullz_bp<4,5,9,4,2,128,3><<<NBP*2, 128, SM4>>>(h3, w4, b4, h4);
    conv4d_point<5,5,6,3,256><<<BATCH, 256, SM5>>>(h4, w5, b5, h5);
    dense_head<<<BATCH, 256>>>(h5, dw1, db1, dw2, db2, out);
}